// round 2
// baseline (speedup 1.0000x reference)
#include <cuda_runtime.h>
#include <math.h>

#define FDIM 128
#define NMAX 400000
#define BMAX 10000

// ---------------- scratch (device globals; no runtime alloc) ----------------
__device__ float g_kq[BMAX * FDIM];   // per-molecule  Wq^T k  vectors
__device__ float g_v [BMAX * FDIM];   // per-molecule  v vectors
__device__ float g_kb[BMAX];          // per-molecule  k·bq
__device__ float g_M [FDIM * 2];      // Wq^T Wk  [F,2]
__device__ float g_mb[2];             // Wk^T bq  [2]
__device__ float g_w [NMAX];          // per-atom logits
__device__ float g_p [NMAX];          // exp(w - wmax)
__device__ float g_anorm[BMAX];       // per-molecule sum of p
__device__ float g_Z;                 // global sum of p
__device__ unsigned g_maxu;           // ordered-bits float max

// monotonic float<->uint mapping for atomicMax over signed floats
__device__ __forceinline__ unsigned f2ord(float f) {
    unsigned b = __float_as_uint(f);
    return (b & 0x80000000u) ? ~b : (b | 0x80000000u);
}
__device__ __forceinline__ float ord2f(unsigned u) {
    unsigned b = (u & 0x80000000u) ? (u & 0x7fffffffu) : ~u;
    return __uint_as_float(b);
}

// shifted softplus: softplus(x) - log(2)
__device__ __forceinline__ float ssp(float x) {
    if (x > 15.f) return x - 0.69314718055994531f;
    return __logf(1.f + __expf(x)) - 0.69314718055994531f;
}

// ---------------- K0: reset accumulators (must run every replay) ------------
__global__ void k_init(int B) {
    int i = blockIdx.x * blockDim.x + threadIdx.x;
    if (i < B) g_anorm[i] = 0.f;
    if (i == 0) { g_Z = 0.f; g_maxu = 0u; }
}

// ---------------- K1: M = Wq^T Wk [F,2],  mb = Wk^T bq ----------------------
__global__ void k_prep(const float* __restrict__ Wq,
                       const float* __restrict__ bq,
                       const float* __restrict__ Wk) {
    int t = threadIdx.x;                 // 256 threads
    int j = t & (FDIM - 1);
    int c = t >> 7;                      // 0 or 1
    float s = 0.f;
    for (int f = 0; f < FDIM; f++) s += Wq[f * FDIM + j] * Wk[f * 2 + c];
    g_M[j * 2 + c] = s;
    if (t < 2) {
        float sb = 0.f;
        for (int f = 0; f < FDIM; f++) sb += Wk[f * 2 + t] * bq[f];
        g_mb[t] = sb;
    }
}

// ---------------- K2: per-molecule kq, v, kb --------------------------------
__global__ void k_mol(const float* __restrict__ ef,
                      const float* __restrict__ Wv, int B) {
    int m = blockIdx.x;
    if (m >= B) return;
    int f = threadIdx.x;                 // 128 threads
    float e  = ef[m];
    float e0 = fmaxf(e, 0.f), e1 = fmaxf(-e, 0.f);
    float h0 = e0 / fmaxf(e0, 1.f), h1 = e1 / fmaxf(e1, 1.f);
    g_kq[m * FDIM + f] = g_M[f * 2 + 0] * h0 + g_M[f * 2 + 1] * h1;
    g_v [m * FDIM + f] = Wv [f * 2 + 0] * e0 + Wv [f * 2 + 1] * e1;
    if (f == 0) g_kb[m] = g_mb[0] * h0 + g_mb[1] * h1;
}

// ---------------- K3: w_n = (kq[m]·x_n + kb[m]) / sqrt(F), track max --------
__global__ void k_w(const float* __restrict__ x,
                    const int* __restrict__ idx, int N) {
    int gw   = (blockIdx.x * blockDim.x + threadIdx.x) >> 5;  // one warp/atom
    int lane = threadIdx.x & 31;
    float wv = -INFINITY;
    if (gw < N) {
        int m = idx[gw];
        const float4* xr = (const float4*)(x + (size_t)gw * FDIM);
        const float4* kr = (const float4*)(g_kq + (size_t)m * FDIM);
        float4 a = xr[lane];
        float4 b = kr[lane];
        float s = a.x * b.x + a.y * b.y + a.z * b.z + a.w * b.w;
        #pragma unroll
        for (int o = 16; o; o >>= 1) s += __shfl_xor_sync(~0u, s, o);
        wv = (s + g_kb[m]) * 0.08838834764831844f;  // 1/sqrt(128)
        if (lane == 0) g_w[gw] = wv;
    }
    __shared__ float red[8];
    if (lane == 0) red[threadIdx.x >> 5] = wv;
    __syncthreads();
    if (threadIdx.x < 8) {
        float v = red[threadIdx.x];
        #pragma unroll
        for (int o = 4; o; o >>= 1) v = fmaxf(v, __shfl_xor_sync(0xffu, v, o));
        if (threadIdx.x == 0) atomicMax(&g_maxu, f2ord(v));
    }
}

// ---------------- K4: p = exp(w - wmax), Z, per-molecule sums ---------------
__global__ void k_p(const int* __restrict__ idx, int N) {
    int n = blockIdx.x * blockDim.x + threadIdx.x;
    float wmax = ord2f(g_maxu);
    float p = 0.f;
    if (n < N) {
        int m = idx[n];
        p = __expf(g_w[n] - wmax);
        g_p[n] = p;
        atomicAdd(&g_anorm[m], p);
    }
    #pragma unroll
    for (int o = 16; o; o >>= 1) p += __shfl_xor_sync(~0u, p, o);
    __shared__ float red[8];
    if ((threadIdx.x & 31) == 0) red[threadIdx.x >> 5] = p;
    __syncthreads();
    if (threadIdx.x < 8) {
        float v = red[threadIdx.x];
        #pragma unroll
        for (int o = 4; o; o >>= 1) v += __shfl_xor_sync(0xffu, v, o);
        if (threadIdx.x == 0) atomicAdd(&g_Z, v);
    }
}

// ---------------- K5: fused residual MLP + output projection ----------------
// out = ssp(x + ssp(ssp(x)@W1^T)@W2^T) @ Wo^T ;  x row = c_n * v[mol(n)]
#define TPAD 132
#define SMEM_BYTES ((3 * 128 * TPAD + 128) * 4 + 128 * 4)

__global__ void __launch_bounds__(256, 1)
k_mlp(const int* __restrict__ idx,
      const float* __restrict__ W1, const float* __restrict__ W2,
      const float* __restrict__ Wo, float* __restrict__ out, int N) {
    extern __shared__ float smem[];
    float* xs = smem;                    // [128][TPAD]  x tile (residual)
    float* hs = xs + 128 * TPAD;         // [128][TPAD]  current activation
    float* wt = hs + 128 * TPAD;         // [128][TPAD]  transposed weight (wt[k][c])
    float* sc = wt + 128 * TPAD;         // [128] per-row coefficient
    int*  smol = (int*)(sc + 128);       // [128] per-row molecule

    int tid = threadIdx.x;
    int n0  = blockIdx.x * 128;

    if (tid < 128) {
        int n = n0 + tid;
        float c = 0.f; int m = 0;
        if (n < N) {
            m = idx[n];
            c = g_p[n] / (g_anorm[m] + 1e-8f * g_Z);
        }
        sc[tid] = c; smol[tid] = m;
    }
    __syncthreads();

    // build x tile and h = ssp(x)
    {
        int r  = tid >> 5;
        int c4 = tid & 31;
        for (int rr = r; rr < 128; rr += 8) {
            float cr = sc[rr];
            const float4* vr = (const float4*)(g_v + (size_t)smol[rr] * FDIM);
            float4 v = vr[c4];
            float4 xv = make_float4(cr * v.x, cr * v.y, cr * v.z, cr * v.w);
            *(float4*)&xs[rr * TPAD + c4 * 4] = xv;
            *(float4*)&hs[rr * TPAD + c4 * 4] =
                make_float4(ssp(xv.x), ssp(xv.y), ssp(xv.z), ssp(xv.w));
        }
    }
    __syncthreads();

    int tr = tid >> 4, tc = tid & 15;
    int r0 = tr * 8, c0 = tc * 8;
    const float* Ws[3] = {W1, W2, Wo};

    for (int s = 0; s < 3; s++) {
        // stage weight into smem, transposed: wt[k][c] = W[c][k]
        const float4* Wg4 = (const float4*)Ws[s];
        for (int i = tid; i < 128 * 32; i += 256) {
            float4 wv = Wg4[i];
            int c = i >> 5, k = (i & 31) << 2;
            wt[(k + 0) * TPAD + c] = wv.x;
            wt[(k + 1) * TPAD + c] = wv.y;
            wt[(k + 2) * TPAD + c] = wv.z;
            wt[(k + 3) * TPAD + c] = wv.w;
        }
        __syncthreads();

        float acc[8][8];
        #pragma unroll
        for (int i = 0; i < 8; i++)
            #pragma unroll
            for (int j = 0; j < 8; j++) acc[i][j] = 0.f;

        for (int k = 0; k < 128; k += 4) {
            float4 a[8];
            #pragma unroll
            for (int i = 0; i < 8; i++)
                a[i] = *(const float4*)&hs[(r0 + i) * TPAD + k];
            float4 b[8];
            #pragma unroll
            for (int kk = 0; kk < 4; kk++) {
                b[2 * kk]     = *(const float4*)&wt[(k + kk) * TPAD + c0];
                b[2 * kk + 1] = *(const float4*)&wt[(k + kk) * TPAD + c0 + 4];
            }
            #pragma unroll
            for (int kk = 0; kk < 4; kk++) {
                #pragma unroll
                for (int i = 0; i < 8; i++) {
                    float ai = ((const float*)&a[i])[kk];
                    acc[i][0] += ai * b[2 * kk].x;
                    acc[i][1] += ai * b[2 * kk].y;
                    acc[i][2] += ai * b[2 * kk].z;
                    acc[i][3] += ai * b[2 * kk].w;
                    acc[i][4] += ai * b[2 * kk + 1].x;
                    acc[i][5] += ai * b[2 * kk + 1].y;
                    acc[i][6] += ai * b[2 * kk + 1].z;
                    acc[i][7] += ai * b[2 * kk + 1].w;
                }
            }
        }
        __syncthreads();   // all reads of hs/wt complete

        if (s == 0) {
            #pragma unroll
            for (int i = 0; i < 8; i++)
                #pragma unroll
                for (int j = 0; j < 8; j++)
                    hs[(r0 + i) * TPAD + c0 + j] = ssp(acc[i][j]);
            __syncthreads();
        } else if (s == 1) {
            #pragma unroll
            for (int i = 0; i < 8; i++)
                #pragma unroll
                for (int j = 0; j < 8; j++)
                    hs[(r0 + i) * TPAD + c0 + j] =
                        ssp(xs[(r0 + i) * TPAD + c0 + j] + acc[i][j]);
            __syncthreads();
        } else {
            #pragma unroll
            for (int i = 0; i < 8; i++) {
                int n = n0 + r0 + i;
                if (n < N) {
                    float4 o0 = make_float4(acc[i][0], acc[i][1], acc[i][2], acc[i][3]);
                    float4 o1 = make_float4(acc[i][4], acc[i][5], acc[i][6], acc[i][7]);
                    *(float4*)&out[(size_t)n * FDIM + c0]     = o0;
                    *(float4*)&out[(size_t)n * FDIM + c0 + 4] = o1;
                }
            }
        }
    }
}

// ---------------- launcher --------------------------------------------------
extern "C" void kernel_launch(void* const* d_in, const int* in_sizes, int n_in,
                              void* d_out, int out_size) {
    const float* x  = (const float*)d_in[0];
    const float* ef = (const float*)d_in[1];
    const int*  idx = (const int*)  d_in[2];
    const float* Wq = (const float*)d_in[3];
    const float* bq = (const float*)d_in[4];
    const float* Wk = (const float*)d_in[5];
    const float* Wv = (const float*)d_in[6];
    const float* W1 = (const float*)d_in[7];
    const float* W2 = (const float*)d_in[8];
    const float* Wo = (const float*)d_in[9];
    float* out = (float*)d_out;

    int N = in_sizes[0] / FDIM;
    int B = in_sizes[1];

    cudaFuncSetAttribute(k_mlp, cudaFuncAttributeMaxDynamicSharedMemorySize,
                         SMEM_BYTES);

    k_init<<<(B + 255) / 256, 256>>>(B);
    k_prep<<<1, 256>>>(Wq, bq, Wk);
    k_mol<<<B, 128>>>(ef, Wv, B);
    k_w<<<(N + 7) / 8, 256>>>(x, idx, N);
    k_p<<<(N + 255) / 256, 256>>>(idx, N);
    k_mlp<<<(N + 127) / 128, 256, SMEM_BYTES>>>(idx, W1, W2, Wo, out, N);
}

// round 3
// speedup vs baseline: 1.0553x; 1.0553x over previous
#include <cuda_runtime.h>
#include <math.h>

#define FDIM 128
#define NMAX 400000
#define BMAX 10000

// ---------------- scratch (device globals; no runtime alloc) ----------------
__device__ float g_kq[BMAX * FDIM];   // per-molecule  Wq^T k  vectors
__device__ float g_v [BMAX * FDIM];   // per-molecule  v vectors
__device__ float g_kb[BMAX];          // per-molecule  k·bq
__device__ float g_M [FDIM * 2];      // Wq^T Wk  [F,2]
__device__ float g_mb[2];             // Wk^T bq  [2]
__device__ float g_w [NMAX];          // per-atom logits
__device__ float g_p [NMAX];          // exp(w - wmax)
__device__ float g_anorm[BMAX];       // per-molecule sum of p
__device__ float g_Z;                 // global sum of p
__device__ unsigned g_maxu;           // ordered-bits float max

// monotonic float<->uint mapping for atomicMax over signed floats
__device__ __forceinline__ unsigned f2ord(float f) {
    unsigned b = __float_as_uint(f);
    return (b & 0x80000000u) ? ~b : (b | 0x80000000u);
}
__device__ __forceinline__ float ord2f(unsigned u) {
    unsigned b = (u & 0x80000000u) ? (u & 0x7fffffffu) : ~u;
    return __uint_as_float(b);
}

// shifted softplus: softplus(x) - log(2)
__device__ __forceinline__ float ssp(float x) {
    if (x > 15.f) return x - 0.69314718055994531f;
    return __logf(1.f + __expf(x)) - 0.69314718055994531f;
}

// packed fp32x2 FMA (FFMA2) — 2 MACs/lane/instr, ptxas never emits this itself
#define FMA2(d, a, b, c) \
    asm("fma.rn.f32x2 %0, %1, %2, %3;" : "=l"(d) : "l"(a), "l"(b), "l"(c))
#define DUP2(d, s) \
    asm("mov.b64 %0, {%1, %1};" : "=l"(d) : "r"(__float_as_uint(s)))
#define UNPK(lo, hi, p) \
    asm("mov.b64 {%0, %1}, %2;" : "=f"(lo), "=f"(hi) : "l"(p))

// ---------------- K0: reset accumulators (must run every replay) ------------
__global__ void k_init(int B) {
    int i = blockIdx.x * blockDim.x + threadIdx.x;
    if (i < B) g_anorm[i] = 0.f;
    if (i == 0) { g_Z = 0.f; g_maxu = 0u; }
}

// ---------------- K1: M = Wq^T Wk [F,2],  mb = Wk^T bq ----------------------
__global__ void k_prep(const float* __restrict__ Wq,
                       const float* __restrict__ bq,
                       const float* __restrict__ Wk) {
    int t = threadIdx.x;                 // 256 threads
    int j = t & (FDIM - 1);
    int c = t >> 7;                      // 0 or 1
    float s = 0.f;
    for (int f = 0; f < FDIM; f++) s += Wq[f * FDIM + j] * Wk[f * 2 + c];
    g_M[j * 2 + c] = s;
    if (t < 2) {
        float sb = 0.f;
        for (int f = 0; f < FDIM; f++) sb += Wk[f * 2 + t] * bq[f];
        g_mb[t] = sb;
    }
}

// ---------------- K2: per-molecule kq, v, kb --------------------------------
__global__ void k_mol(const float* __restrict__ ef,
                      const float* __restrict__ Wv, int B) {
    int m = blockIdx.x;
    if (m >= B) return;
    int f = threadIdx.x;                 // 128 threads
    float e  = ef[m];
    float e0 = fmaxf(e, 0.f), e1 = fmaxf(-e, 0.f);
    float h0 = e0 / fmaxf(e0, 1.f), h1 = e1 / fmaxf(e1, 1.f);
    g_kq[m * FDIM + f] = g_M[f * 2 + 0] * h0 + g_M[f * 2 + 1] * h1;
    g_v [m * FDIM + f] = Wv [f * 2 + 0] * e0 + Wv [f * 2 + 1] * e1;
    if (f == 0) g_kb[m] = g_mb[0] * h0 + g_mb[1] * h1;
}

// ---------------- K3: w_n = (kq[m]·x_n + kb[m]) / sqrt(F), track max --------
// 4 atoms per warp for MLP=8 outstanding loads
__global__ void k_w(const float* __restrict__ x,
                    const int* __restrict__ idx, int N) {
    int warp = (blockIdx.x * blockDim.x + threadIdx.x) >> 5;
    int lane = threadIdx.x & 31;
    int base = warp * 4;
    float wmaxl = -INFINITY;

    if (base < N) {
        float s[4];
        int   m[4];
        #pragma unroll
        for (int j = 0; j < 4; j++) {
            int n = base + j;
            s[j] = 0.f; m[j] = 0;
            if (n < N) {
                m[j] = idx[n];
                float4 a = ((const float4*)(x    + (size_t)n    * FDIM))[lane];
                float4 b = ((const float4*)(g_kq + (size_t)m[j] * FDIM))[lane];
                s[j] = a.x * b.x + a.y * b.y + a.z * b.z + a.w * b.w;
            }
        }
        #pragma unroll
        for (int j = 0; j < 4; j++) {
            #pragma unroll
            for (int o = 16; o; o >>= 1) s[j] += __shfl_xor_sync(~0u, s[j], o);
        }
        #pragma unroll
        for (int j = 0; j < 4; j++) {
            int n = base + j;
            if (n < N) {
                float wv = (s[j] + g_kb[m[j]]) * 0.08838834764831844f;
                if (lane == j) g_w[n] = wv;
                wmaxl = fmaxf(wmaxl, wv);
            }
        }
    }
    __shared__ float red[8];
    if (lane == 0) red[threadIdx.x >> 5] = wmaxl;
    __syncthreads();
    if (threadIdx.x < 8) {
        float v = red[threadIdx.x];
        #pragma unroll
        for (int o = 4; o; o >>= 1) v = fmaxf(v, __shfl_xor_sync(0xffu, v, o));
        if (threadIdx.x == 0) atomicMax(&g_maxu, f2ord(v));
    }
}

// ---------------- K4: p = exp(w - wmax), Z, per-molecule sums ---------------
__global__ void k_p(const int* __restrict__ idx, int N) {
    int n = blockIdx.x * blockDim.x + threadIdx.x;
    float wmax = ord2f(g_maxu);
    float p = 0.f;
    if (n < N) {
        int m = idx[n];
        p = __expf(g_w[n] - wmax);
        g_p[n] = p;
        atomicAdd(&g_anorm[m], p);
    }
    #pragma unroll
    for (int o = 16; o; o >>= 1) p += __shfl_xor_sync(~0u, p, o);
    __shared__ float red[8];
    if ((threadIdx.x & 31) == 0) red[threadIdx.x >> 5] = p;
    __syncthreads();
    if (threadIdx.x < 8) {
        float v = red[threadIdx.x];
        #pragma unroll
        for (int o = 4; o; o >>= 1) v += __shfl_xor_sync(0xffu, v, o);
        if (threadIdx.x == 0) atomicAdd(&g_Z, v);
    }
}

// ---------------- K5: fused residual MLP + output projection ----------------
// out = ssp(x + ssp(ssp(x)@W1^T)@W2^T) @ Wo^T ;  x row = c_n * v[mol(n)]
#define TPAD 132
#define SMEM_BYTES ((3 * 128 * TPAD + 128) * 4 + 128 * 4)

__global__ void __launch_bounds__(256, 1)
k_mlp(const int* __restrict__ idx,
      const float* __restrict__ W1, const float* __restrict__ W2,
      const float* __restrict__ Wo, float* __restrict__ out, int N) {
    extern __shared__ float smem[];
    float* xs = smem;                    // [128][TPAD]  x tile (residual)
    float* hs = xs + 128 * TPAD;         // [128][TPAD]  current activation
    float* wt = hs + 128 * TPAD;         // [128][TPAD]  transposed weight (wt[k][c])
    float* sc = wt + 128 * TPAD;         // [128] per-row coefficient
    int*  smol = (int*)(sc + 128);       // [128] per-row molecule

    int tid = threadIdx.x;
    int n0  = blockIdx.x * 128;

    if (tid < 128) {
        int n = n0 + tid;
        float c = 0.f; int m = 0;
        if (n < N) {
            m = idx[n];
            c = g_p[n] / (g_anorm[m] + 1e-8f * g_Z);
        }
        sc[tid] = c; smol[tid] = m;
    }
    __syncthreads();

    // build x tile and h = ssp(x)
    {
        int r  = tid >> 5;
        int c4 = tid & 31;
        for (int rr = r; rr < 128; rr += 8) {
            float cr = sc[rr];
            const float4* vr = (const float4*)(g_v + (size_t)smol[rr] * FDIM);
            float4 v = vr[c4];
            float4 xv = make_float4(cr * v.x, cr * v.y, cr * v.z, cr * v.w);
            *(float4*)&xs[rr * TPAD + c4 * 4] = xv;
            *(float4*)&hs[rr * TPAD + c4 * 4] =
                make_float4(ssp(xv.x), ssp(xv.y), ssp(xv.z), ssp(xv.w));
        }
    }
    __syncthreads();

    int tr = tid >> 4, tc = tid & 15;
    int r0 = tr * 8, c0 = tc * 8;
    const float* Ws[3] = {W1, W2, Wo};

    for (int s = 0; s < 3; s++) {
        // stage weight into smem, transposed: wt[k][c] = W[c][k]
        const float4* Wg4 = (const float4*)Ws[s];
        for (int i = tid; i < 128 * 32; i += 256) {
            float4 wv = Wg4[i];
            int c = i >> 5, k = (i & 31) << 2;
            wt[(k + 0) * TPAD + c] = wv.x;
            wt[(k + 1) * TPAD + c] = wv.y;
            wt[(k + 2) * TPAD + c] = wv.z;
            wt[(k + 3) * TPAD + c] = wv.w;
        }
        __syncthreads();

        // 8x8 microtile, accumulators as 8 rows x 4 packed f32x2 col-pairs
        unsigned long long acc2[8][4];
        #pragma unroll
        for (int i = 0; i < 8; i++)
            #pragma unroll
            for (int j = 0; j < 4; j++) acc2[i][j] = 0ull;

        for (int k = 0; k < 128; k += 4) {
            float4 a[8];
            #pragma unroll
            for (int i = 0; i < 8; i++)
                a[i] = *(const float4*)&hs[(r0 + i) * TPAD + k];
            #pragma unroll
            for (int kk = 0; kk < 4; kk++) {
                // B pairs loaded pre-packed from smem (16B aligned)
                ulonglong2 q0 = *(const ulonglong2*)&wt[(k + kk) * TPAD + c0];
                ulonglong2 q1 = *(const ulonglong2*)&wt[(k + kk) * TPAD + c0 + 4];
                #pragma unroll
                for (int i = 0; i < 8; i++) {
                    float ai = ((const float*)&a[i])[kk];
                    unsigned long long ad;
                    DUP2(ad, ai);
                    FMA2(acc2[i][0], ad, q0.x, acc2[i][0]);
                    FMA2(acc2[i][1], ad, q0.y, acc2[i][1]);
                    FMA2(acc2[i][2], ad, q1.x, acc2[i][2]);
                    FMA2(acc2[i][3], ad, q1.y, acc2[i][3]);
                }
            }
        }
        __syncthreads();   // all reads of hs/wt complete

        if (s == 0) {
            #pragma unroll
            for (int i = 0; i < 8; i++)
                #pragma unroll
                for (int j = 0; j < 4; j++) {
                    float lo, hi;
                    UNPK(lo, hi, acc2[i][j]);
                    hs[(r0 + i) * TPAD + c0 + 2 * j]     = ssp(lo);
                    hs[(r0 + i) * TPAD + c0 + 2 * j + 1] = ssp(hi);
                }
            __syncthreads();
        } else if (s == 1) {
            #pragma unroll
            for (int i = 0; i < 8; i++)
                #pragma unroll
                for (int j = 0; j < 4; j++) {
                    float lo, hi;
                    UNPK(lo, hi, acc2[i][j]);
                    hs[(r0 + i) * TPAD + c0 + 2 * j] =
                        ssp(xs[(r0 + i) * TPAD + c0 + 2 * j] + lo);
                    hs[(r0 + i) * TPAD + c0 + 2 * j + 1] =
                        ssp(xs[(r0 + i) * TPAD + c0 + 2 * j + 1] + hi);
                }
            __syncthreads();
        } else {
            #pragma unroll
            for (int i = 0; i < 8; i++) {
                int n = n0 + r0 + i;
                if (n < N) {
                    float o[8];
                    #pragma unroll
                    for (int j = 0; j < 4; j++)
                        UNPK(o[2 * j], o[2 * j + 1], acc2[i][j]);
                    *(float4*)&out[(size_t)n * FDIM + c0] =
                        make_float4(o[0], o[1], o[2], o[3]);
                    *(float4*)&out[(size_t)n * FDIM + c0 + 4] =
                        make_float4(o[4], o[5], o[6], o[7]);
                }
            }
        }
    }
}

// ---------------- launcher --------------------------------------------------
extern "C" void kernel_launch(void* const* d_in, const int* in_sizes, int n_in,
                              void* d_out, int out_size) {
    const float* x  = (const float*)d_in[0];
    const float* ef = (const float*)d_in[1];
    const int*  idx = (const int*)  d_in[2];
    const float* Wq = (const float*)d_in[3];
    const float* bq = (const float*)d_in[4];
    const float* Wk = (const float*)d_in[5];
    const float* Wv = (const float*)d_in[6];
    const float* W1 = (const float*)d_in[7];
    const float* W2 = (const float*)d_in[8];
    const float* Wo = (const float*)d_in[9];
    float* out = (float*)d_out;

    int N = in_sizes[0] / FDIM;
    int B = in_sizes[1];

    cudaFuncSetAttribute(k_mlp, cudaFuncAttributeMaxDynamicSharedMemorySize,
                         SMEM_BYTES);

    k_init<<<(B + 255) / 256, 256>>>(B);
    k_prep<<<1, 256>>>(Wq, bq, Wk);
    k_mol<<<B, 128>>>(ef, Wv, B);
    k_w<<<(N + 31) / 32, 256>>>(x, idx, N);
    k_p<<<(N + 255) / 256, 256>>>(idx, N);
    k_mlp<<<(N + 127) / 128, 256, SMEM_BYTES>>>(idx, W1, W2, Wo, out, N);
}

// round 9
// speedup vs baseline: 2.9693x; 2.8136x over previous
#include <cuda_runtime.h>
#include <cuda_bf16.h>
#include <math.h>

#define FDIM 128
#define NMAX 400000
#define BMAX 10000
#define APAD 136

// ---------------- scratch (device globals; no runtime alloc) ----------------
__device__ float g_kq[BMAX * FDIM];
__device__ float g_v [BMAX * FDIM];
__device__ float g_kb[BMAX];
__device__ float g_M [FDIM * 2];
__device__ float g_mb[2];
__device__ float g_w [NMAX];
__device__ float g_p [NMAX];
__device__ float g_anorm[BMAX];
__device__ float g_Z;
__device__ unsigned g_maxu;
// B fragments in per-lane mma layout: [3 stages][8 ksteps][16 ntiles][32 lanes]
// uint4 = { bh0, bh1, bl0, bl1 }
__device__ uint4 g_Bf[3 * 8 * 16 * 32];

// ---------------- small helpers ---------------------------------------------
__device__ __forceinline__ unsigned f2ord(float f) {
    unsigned b = __float_as_uint(f);
    return (b & 0x80000000u) ? ~b : (b | 0x80000000u);
}
__device__ __forceinline__ float ord2f(unsigned u) {
    unsigned b = (u & 0x80000000u) ? (u & 0x7fffffffu) : ~u;
    return __uint_as_float(b);
}
__device__ __forceinline__ float ssp(float x) {
    if (x > 15.f) return x - 0.69314718055994531f;
    return __logf(1.f + __expf(x)) - 0.69314718055994531f;
}
__device__ __forceinline__ unsigned smem_u32(const void* p) {
    unsigned a;
    asm("{ .reg .u64 t; cvta.to.shared.u64 t, %1; cvt.u32.u64 %0, t; }"
        : "=r"(a) : "l"(p));
    return a;
}
__device__ __forceinline__ unsigned pack_bf2(float a, float b) {
    __nv_bfloat162 h = __halves2bfloat162(__float2bfloat16(a), __float2bfloat16(b));
    return *(unsigned*)&h;
}

// mma.sync m16n8k16 row.col bf16 -> f32 accum (arch-generic, works at sm_103)
#define MMA16816(c0, c1, c2, c3, a0, a1, a2, a3, b0, b1) \
    asm volatile("mma.sync.aligned.m16n8k16.row.col.f32.bf16.bf16.f32 " \
                 "{%0,%1,%2,%3},{%4,%5,%6,%7},{%8,%9},{%0,%1,%2,%3};" \
                 : "+f"(c0), "+f"(c1), "+f"(c2), "+f"(c3) \
                 : "r"(a0), "r"(a1), "r"(a2), "r"(a3), "r"(b0), "r"(b1))

#define LDMATRIX_X4(r0, r1, r2, r3, addr) \
    asm volatile("ldmatrix.sync.aligned.m8n8.x4.shared.b16 {%0,%1,%2,%3}, [%4];" \
                 : "=r"(r0), "=r"(r1), "=r"(r2), "=r"(r3) : "r"(addr))

// ---------------- K0: reset accumulators ------------------------------------
__global__ void k_init(int B) {
    int i = blockIdx.x * blockDim.x + threadIdx.x;
    if (i < B) g_anorm[i] = 0.f;
    if (i == 0) { g_Z = 0.f; g_maxu = 0u; }
}

// ---------------- K1: M = Wq^T Wk,  mb = Wk^T bq ----------------------------
__global__ void k_prep(const float* __restrict__ Wq,
                       const float* __restrict__ bq,
                       const float* __restrict__ Wk) {
    int t = threadIdx.x;
    int j = t & (FDIM - 1);
    int c = t >> 7;
    float s = 0.f;
    for (int f = 0; f < FDIM; f++) s += Wq[f * FDIM + j] * Wk[f * 2 + c];
    g_M[j * 2 + c] = s;
    if (t < 2) {
        float sb = 0.f;
        for (int f = 0; f < FDIM; f++) sb += Wk[f * 2 + t] * bq[f];
        g_mb[t] = sb;
    }
}

// ---------------- K1b: weights -> bf16 hi/lo B fragments --------------------
// B[k][n] = W[n][k]; mma B frag: b0 <- k=(l%4)*2+{0,1}, b1 <- k=+8; n = l/4
__global__ void k_wconv(const float* __restrict__ W1,
                        const float* __restrict__ W2,
                        const float* __restrict__ Wo) {
    int i = blockIdx.x * blockDim.x + threadIdx.x;   // 3*8*16*32 = 12288
    if (i >= 12288) return;
    int lane = i & 31, t = (i >> 5) & 15, ks = (i >> 9) & 7, s = i >> 12;
    const float* W = (s == 0) ? W1 : ((s == 1) ? W2 : Wo);
    int n  = t * 8 + (lane >> 2);
    int k0 = ks * 16 + (lane & 3) * 2;
    const float* row = W + n * FDIM;

    float w00 = row[k0],     w01 = row[k0 + 1];
    float w10 = row[k0 + 8], w11 = row[k0 + 9];
    float h00 = __bfloat162float(__float2bfloat16(w00));
    float h01 = __bfloat162float(__float2bfloat16(w01));
    float h10 = __bfloat162float(__float2bfloat16(w10));
    float h11 = __bfloat162float(__float2bfloat16(w11));

    uint4 o;
    o.x = pack_bf2(w00, w01);
    o.y = pack_bf2(w10, w11);
    o.z = pack_bf2(w00 - h00, w01 - h01);
    o.w = pack_bf2(w10 - h10, w11 - h11);
    g_Bf[i] = o;
}

// ---------------- K2: per-molecule kq, v, kb --------------------------------
__global__ void k_mol(const float* __restrict__ ef,
                      const float* __restrict__ Wv, int B) {
    int m = blockIdx.x;
    if (m >= B) return;
    int f = threadIdx.x;
    float e  = ef[m];
    float e0 = fmaxf(e, 0.f), e1 = fmaxf(-e, 0.f);
    float h0 = e0 / fmaxf(e0, 1.f), h1 = e1 / fmaxf(e1, 1.f);
    g_kq[m * FDIM + f] = g_M[f * 2 + 0] * h0 + g_M[f * 2 + 1] * h1;
    g_v [m * FDIM + f] = Wv [f * 2 + 0] * e0 + Wv [f * 2 + 1] * e1;
    if (f == 0) g_kb[m] = g_mb[0] * h0 + g_mb[1] * h1;
}

// ---------------- K3: logits + global max -----------------------------------
__global__ void k_w(const float* __restrict__ x,
                    const int* __restrict__ idx, int N) {
    int warp = (blockIdx.x * blockDim.x + threadIdx.x) >> 5;
    int lane = threadIdx.x & 31;
    int base = warp * 4;
    float wmaxl = -INFINITY;

    if (base < N) {
        float s[4];
        int   m[4];
        #pragma unroll
        for (int j = 0; j < 4; j++) {
            int n = base + j;
            s[j] = 0.f; m[j] = 0;
            if (n < N) {
                m[j] = idx[n];
                float4 a = ((const float4*)(x    + (size_t)n    * FDIM))[lane];
                float4 b = ((const float4*)(g_kq + (size_t)m[j] * FDIM))[lane];
                s[j] = a.x * b.x + a.y * b.y + a.z * b.z + a.w * b.w;
            }
        }
        #pragma unroll
        for (int j = 0; j < 4; j++) {
            #pragma unroll
            for (int o = 16; o; o >>= 1) s[j] += __shfl_xor_sync(~0u, s[j], o);
        }
        #pragma unroll
        for (int j = 0; j < 4; j++) {
            int n = base + j;
            if (n < N) {
                float wv = (s[j] + g_kb[m[j]]) * 0.08838834764831844f;
                if (lane == j) g_w[n] = wv;
                wmaxl = fmaxf(wmaxl, wv);
            }
        }
    }
    __shared__ float red[8];
    if (lane == 0) red[threadIdx.x >> 5] = wmaxl;
    __syncthreads();
    if (threadIdx.x < 8) {
        float v = red[threadIdx.x];
        #pragma unroll
        for (int o = 4; o; o >>= 1) v = fmaxf(v, __shfl_xor_sync(0xffu, v, o));
        if (threadIdx.x == 0) atomicMax(&g_maxu, f2ord(v));
    }
}

// ---------------- K4: p = exp(w - wmax), Z, per-molecule sums ---------------
__global__ void k_p(const int* __restrict__ idx, int N) {
    int n = blockIdx.x * blockDim.x + threadIdx.x;
    float wmax = ord2f(g_maxu);
    float p = 0.f;
    if (n < N) {
        int m = idx[n];
        p = __expf(g_w[n] - wmax);
        g_p[n] = p;
        atomicAdd(&g_anorm[m], p);
    }
    #pragma unroll
    for (int o = 16; o; o >>= 1) p += __shfl_xor_sync(~0u, p, o);
    __shared__ float red[8];
    if ((threadIdx.x & 31) == 0) red[threadIdx.x >> 5] = p;
    __syncthreads();
    if (threadIdx.x < 8) {
        float v = red[threadIdx.x];
        #pragma unroll
        for (int o = 4; o; o >>= 1) v += __shfl_xor_sync(0xffu, v, o);
        if (threadIdx.x == 0) atomicAdd(&g_Z, v);
    }
}

// ---------------- K5: fused residual MLP via mma.sync bf16-split ------------
// smem: sc[128] | smol[128] | Ah[128][APAD] bf16 | Al[128][APAD] bf16
#define OFF_SC  0
#define OFF_MOL 512
#define OFF_AH  1024
#define OFF_AL  (OFF_AH + 128 * APAD * 2)
#define SMEM_TOTAL (OFF_AL + 128 * APAD * 2)

__device__ __forceinline__ void st_pair(char* sm, int r, int c, float a, float b) {
    float ha = __bfloat162float(__float2bfloat16(a));
    float hb = __bfloat162float(__float2bfloat16(b));
    unsigned off = (unsigned)(r * APAD + c) * 2u;
    *(unsigned*)(sm + OFF_AH + off) = pack_bf2(a, b);
    *(unsigned*)(sm + OFF_AL + off) = pack_bf2(a - ha, b - hb);
}

__global__ void __launch_bounds__(256, 2)
k_mlp(const int* __restrict__ idx, float* __restrict__ out, int N) {
    extern __shared__ char sm[];
    float* sc   = (float*)(sm + OFF_SC);
    int*   smol = (int*)  (sm + OFF_MOL);
    int tid = threadIdx.x, wid = tid >> 5, lane = tid & 31;
    int n0 = blockIdx.x * 128;
    int r0 = wid * 16;

    if (tid < 128) {
        int n = n0 + tid; float c = 0.f; int m = 0;
        if (n < N) { m = idx[n]; c = g_p[n] / (g_anorm[m] + 1e-8f * g_Z); }
        sc[tid] = c; smol[tid] = m;
    }
    __syncthreads();

    // build stage-0 A tiles: ssp(c * v) -> bf16 hi/lo (warp-local rows)
    {
        int r = tid >> 1, co = (tid & 1) * 64;
        float c = sc[r];
        const float4* vr = (const float4*)(g_v + (size_t)smol[r] * FDIM + co);
        #pragma unroll
        for (int q = 0; q < 16; q++) {
            float4 v = vr[q];
            int j = co + q * 4;
            st_pair(sm, r, j,     ssp(c * v.x), ssp(c * v.y));
            st_pair(sm, r, j + 2, ssp(c * v.z), ssp(c * v.w));
        }
    }
    __syncwarp();

    // ldmatrix source address for this lane (A frag m16k16, 4 8x8 tiles)
    int lrow = r0 + (lane & 7) + ((lane >> 3) & 1) * 8;
    int lkof = (lane >> 4) * 8;
    unsigned aAh = smem_u32(sm + OFF_AH) + (unsigned)(lrow * APAD + lkof) * 2u;
    unsigned aAl = smem_u32(sm + OFF_AL) + (unsigned)(lrow * APAD + lkof) * 2u;

    int gr0 = r0 + (lane >> 2);        // epilogue rows
    int gr1 = gr0 + 8;
    int cofs = (lane & 3) * 2;         // epilogue col offset inside n-tile

    for (int s = 0; s < 3; s++) {
        float acc[16][4];
        #pragma unroll
        for (int t = 0; t < 16; t++) {
            acc[t][0] = 0.f; acc[t][1] = 0.f; acc[t][2] = 0.f; acc[t][3] = 0.f;
        }
        const uint4* Bp = g_Bf + (s * 8) * 16 * 32 + lane;

        #pragma unroll
        for (int ks = 0; ks < 8; ks++) {
            unsigned ah0, ah1, ah2, ah3, al0, al1, al2, al3;
            unsigned koff = (unsigned)(ks * 16) * 2u;
            LDMATRIX_X4(ah0, ah1, ah2, ah3, aAh + koff);
            LDMATRIX_X4(al0, al1, al2, al3, aAl + koff);
            #pragma unroll
            for (int t = 0; t < 16; t++) {
                uint4 b = Bp[(ks * 16 + t) * 32];
                MMA16816(acc[t][0], acc[t][1], acc[t][2], acc[t][3],
                         ah0, ah1, ah2, ah3, b.x, b.y);   // Ah*Bh
                MMA16816(acc[t][0], acc[t][1], acc[t][2], acc[t][3],
                         ah0, ah1, ah2, ah3, b.z, b.w);   // Ah*Bl
                MMA16816(acc[t][0], acc[t][1], acc[t][2], acc[t][3],
                         al0, al1, al2, al3, b.x, b.y);   // Al*Bh
            }
        }

        if (s == 2) {
            #pragma unroll
            for (int t = 0; t < 16; t++) {
                int c = t * 8 + cofs;
                int na = n0 + gr0, nb = n0 + gr1;
                if (na < N)
                    *(float2*)(out + (size_t)na * FDIM + c) =
                        make_float2(acc[t][0], acc[t][1]);
                if (nb < N)
                    *(float2*)(out + (size_t)nb * FDIM + c) =
                        make_float2(acc[t][2], acc[t][3]);
            }
        } else if (s == 0) {
            #pragma unroll
            for (int t = 0; t < 16; t++) {
                int c = t * 8 + cofs;
                st_pair(sm, gr0, c, ssp(acc[t][0]), ssp(acc[t][1]));
                st_pair(sm, gr1, c, ssp(acc[t][2]), ssp(acc[t][3]));
            }
            __syncwarp();
        } else {
            float ca = sc[gr0], cb = sc[gr1];
            const float* va = g_v + (size_t)smol[gr0] * FDIM;
            const float* vb = g_v + (size_t)smol[gr1] * FDIM;
            #pragma unroll
            for (int t = 0; t < 16; t++) {
                int c = t * 8 + cofs;
                float2 v0 = *(const float2*)(va + c);
                float2 v1 = *(const float2*)(vb + c);
                st_pair(sm, gr0, c, ssp(ca * v0.x + acc[t][0]),
                                    ssp(ca * v0.y + acc[t][1]));
                st_pair(sm, gr1, c, ssp(cb * v1.x + acc[t][2]),
                                    ssp(cb * v1.y + acc[t][3]));
            }
            __syncwarp();
        }
    }
}

// ---------------- launcher --------------------------------------------------
extern "C" void kernel_launch(void* const* d_in, const int* in_sizes, int n_in,
                              void* d_out, int out_size) {
    const float* x  = (const float*)d_in[0];
    const float* ef = (const float*)d_in[1];
    const int*  idx = (const int*)  d_in[2];
    const float* Wq = (const float*)d_in[3];
    const float* bq = (const float*)d_in[4];
    const float* Wk = (const float*)d_in[5];
    const float* Wv = (const float*)d_in[6];
    const float* W1 = (const float*)d_in[7];
    const float* W2 = (const float*)d_in[8];
    const float* Wo = (const float*)d_in[9];
    float* out = (float*)d_out;

    int N = in_sizes[0] / FDIM;
    int B = in_sizes[1];

    cudaFuncSetAttribute(k_mlp, cudaFuncAttributeMaxDynamicSharedMemorySize,
                         SMEM_TOTAL);

    k_init<<<(B + 255) / 256, 256>>>(B);
    k_prep<<<1, 256>>>(Wq, bq, Wk);
    k_wconv<<<48, 256>>>(W1, W2, Wo);
    k_mol<<<B, 128>>>(ef, Wv, B);
    k_w<<<(N + 31) / 32, 256>>>(x, idx, N);
    k_p<<<(N + 255) / 256, 256>>>(idx, N);
    k_mlp<<<(N + 127) / 128, 256, SMEM_TOTAL>>>(idx, out, N);
}

// round 10
// speedup vs baseline: 3.6604x; 1.2328x over previous
#include <cuda_runtime.h>
#include <cuda_fp16.h>
#include <math.h>

#define FDIM 128
#define NMAX 400000
#define BMAX 10000
#define APAD 136

// ---------------- scratch (device globals; no runtime alloc) ----------------
__device__ float g_kq[BMAX * FDIM];
__device__ float g_v [BMAX * FDIM];
__device__ float g_kb[BMAX];
__device__ float g_M [FDIM * 2];
__device__ float g_mb[2];
__device__ float g_w [NMAX];
__device__ float g_p [NMAX];
__device__ float g_anorm[BMAX];
__device__ float g_Z;
__device__ unsigned g_maxu;
// B fragments, per-lane mma layout: [3 stages][8 ksteps][16 ntiles][32 lanes]
// uint4 = { bh0, bh1, bl0, bl1 }  (fp16 hi / fp16 residual)
__device__ uint4 g_Bf[3 * 8 * 16 * 32];

// ---------------- small helpers ---------------------------------------------
__device__ __forceinline__ unsigned f2ord(float f) {
    unsigned b = __float_as_uint(f);
    return (b & 0x80000000u) ? ~b : (b | 0x80000000u);
}
__device__ __forceinline__ float ord2f(unsigned u) {
    unsigned b = (u & 0x80000000u) ? (u & 0x7fffffffu) : ~u;
    return __uint_as_float(b);
}
__device__ __forceinline__ float ssp(float x) {
    if (x > 15.f) return x - 0.69314718055994531f;
    return __logf(1.f + __expf(x)) - 0.69314718055994531f;
}
__device__ __forceinline__ unsigned smem_u32(const void* p) {
    unsigned a;
    asm("{ .reg .u64 t; cvta.to.shared.u64 t, %1; cvt.u32.u64 %0, t; }"
        : "=r"(a) : "l"(p));
    return a;
}
__device__ __forceinline__ unsigned pack_h2(float a, float b) {
    __half2 h = __halves2half2(__float2half_rn(a), __float2half_rn(b));
    return *(unsigned*)&h;
}

// mma.sync m16n8k16 row.col fp16 -> f32 accum (arch-generic, valid at sm_103)
#define MMA16816(c0, c1, c2, c3, a0, a1, a2, a3, b0, b1) \
    asm volatile("mma.sync.aligned.m16n8k16.row.col.f32.f16.f16.f32 " \
                 "{%0,%1,%2,%3},{%4,%5,%6,%7},{%8,%9},{%0,%1,%2,%3};" \
                 : "+f"(c0), "+f"(c1), "+f"(c2), "+f"(c3) \
                 : "r"(a0), "r"(a1), "r"(a2), "r"(a3), "r"(b0), "r"(b1))

#define LDMATRIX_X4(r0, r1, r2, r3, addr) \
    asm volatile("ldmatrix.sync.aligned.m8n8.x4.shared.b16 {%0,%1,%2,%3}, [%4];" \
                 : "=r"(r0), "=r"(r1), "=r"(r2), "=r"(r3) : "r"(addr))

// ---------------- K_setup: init accumulators + prep M/mb + weight conv ------
// blocks [0,48): B-frag conversion; block 48: M/mb; blocks 49..: zero anorm
__global__ void k_setup(const float* __restrict__ Wq,
                        const float* __restrict__ bq,
                        const float* __restrict__ Wk,
                        const float* __restrict__ W1,
                        const float* __restrict__ W2,
                        const float* __restrict__ Wo, int B) {
    int blk = blockIdx.x, tid = threadIdx.x;
    if (blk < 48) {
        int i = blk * 256 + tid;                     // 12288 fragments
        int lane = i & 31, t = (i >> 5) & 15, ks = (i >> 9) & 7, s = i >> 12;
        const float* W = (s == 0) ? W1 : ((s == 1) ? W2 : Wo);
        int n  = t * 8 + (lane >> 2);
        int k0 = ks * 16 + (lane & 3) * 2;
        const float* row = W + n * FDIM;
        float w00 = row[k0],     w01 = row[k0 + 1];
        float w10 = row[k0 + 8], w11 = row[k0 + 9];
        float h00 = __half2float(__float2half_rn(w00));
        float h01 = __half2float(__float2half_rn(w01));
        float h10 = __half2float(__float2half_rn(w10));
        float h11 = __half2float(__float2half_rn(w11));
        uint4 o;
        o.x = pack_h2(w00, w01);
        o.y = pack_h2(w10, w11);
        o.z = pack_h2(w00 - h00, w01 - h01);
        o.w = pack_h2(w10 - h10, w11 - h11);
        g_Bf[i] = o;
    } else if (blk == 48) {
        int j = tid & (FDIM - 1);
        int c = tid >> 7;
        float s = 0.f;
        for (int f = 0; f < FDIM; f++) s += Wq[f * FDIM + j] * Wk[f * 2 + c];
        g_M[j * 2 + c] = s;
        if (tid < 2) {
            float sb = 0.f;
            for (int f = 0; f < FDIM; f++) sb += Wk[f * 2 + tid] * bq[f];
            g_mb[tid] = sb;
        }
    } else {
        int i = (blk - 49) * 256 + tid;
        if (i < B) g_anorm[i] = 0.f;
        if (i == 0) { g_Z = 0.f; g_maxu = 0u; }
    }
}

// ---------------- K2: per-molecule kq, v, kb --------------------------------
__global__ void k_mol(const float* __restrict__ ef,
                      const float* __restrict__ Wv, int B) {
    int i = blockIdx.x * blockDim.x + threadIdx.x;
    if (i >= B * FDIM) return;
    int m = i >> 7, f = i & (FDIM - 1);
    float e  = ef[m];
    float e0 = fmaxf(e, 0.f), e1 = fmaxf(-e, 0.f);
    float h0 = e0 / fmaxf(e0, 1.f), h1 = e1 / fmaxf(e1, 1.f);
    g_kq[i] = g_M[f * 2 + 0] * h0 + g_M[f * 2 + 1] * h1;
    g_v [i] = Wv [f * 2 + 0] * e0 + Wv [f * 2 + 1] * e1;
    if (f == 0) g_kb[m] = g_mb[0] * h0 + g_mb[1] * h1;
}

// ---------------- K3: logits + global max (8 atoms / warp) ------------------
__global__ void k_w(const float* __restrict__ x,
                    const int* __restrict__ idx, int N) {
    int warp = (blockIdx.x * blockDim.x + threadIdx.x) >> 5;
    int lane = threadIdx.x & 31;
    int base = warp * 8;
    float wmaxl = -INFINITY;

    if (base < N) {
        float s[8];
        int   m[8];
        #pragma unroll
        for (int j = 0; j < 8; j++) {
            int n = base + j;
            s[j] = 0.f; m[j] = 0;
            if (n < N) {
                m[j] = idx[n];
                float4 a = ((const float4*)(x    + (size_t)n    * FDIM))[lane];
                float4 b = ((const float4*)(g_kq + (size_t)m[j] * FDIM))[lane];
                s[j] = a.x * b.x + a.y * b.y + a.z * b.z + a.w * b.w;
            }
        }
        #pragma unroll
        for (int j = 0; j < 8; j++) {
            #pragma unroll
            for (int o = 16; o; o >>= 1) s[j] += __shfl_xor_sync(~0u, s[j], o);
        }
        #pragma unroll
        for (int j = 0; j < 8; j++) {
            int n = base + j;
            if (n < N) {
                float wv = (s[j] + g_kb[m[j]]) * 0.08838834764831844f;
                if (lane == j) g_w[n] = wv;
                wmaxl = fmaxf(wmaxl, wv);
            }
        }
    }
    __shared__ float red[8];
    if (lane == 0) red[threadIdx.x >> 5] = wmaxl;
    __syncthreads();
    if (threadIdx.x < 8) {
        float v = red[threadIdx.x];
        #pragma unroll
        for (int o = 4; o; o >>= 1) v = fmaxf(v, __shfl_xor_sync(0xffu, v, o));
        if (threadIdx.x == 0) atomicMax(&g_maxu, f2ord(v));
    }
}

// ---------------- K4: p = exp(w - wmax), Z, per-molecule sums ---------------
__global__ void k_p(const int* __restrict__ idx, int N) {
    int n = blockIdx.x * blockDim.x + threadIdx.x;
    int lane = threadIdx.x & 31;
    float wmax = ord2f(g_maxu);
    float p = 0.f; int m = -1;
    if (n < N) {
        m = idx[n];
        p = __expf(g_w[n] - wmax);
        g_p[n] = p;
    }
    // warp-aggregated segment atomic (idx sorted -> most warps uniform)
    int mf = __shfl_sync(~0u, m, 0);
    if (__all_sync(~0u, m == mf)) {
        float t = p;
        #pragma unroll
        for (int o = 16; o; o >>= 1) t += __shfl_xor_sync(~0u, t, o);
        if (lane == 0 && mf >= 0) atomicAdd(&g_anorm[mf], t);
    } else if (n < N) {
        atomicAdd(&g_anorm[m], p);
    }
    // global Z
    float z = p;
    #pragma unroll
    for (int o = 16; o; o >>= 1) z += __shfl_xor_sync(~0u, z, o);
    __shared__ float red[8];
    if (lane == 0) red[threadIdx.x >> 5] = z;
    __syncthreads();
    if (threadIdx.x < 8) {
        float v = red[threadIdx.x];
        #pragma unroll
        for (int o = 4; o; o >>= 1) v += __shfl_xor_sync(0xffu, v, o);
        if (threadIdx.x == 0) atomicAdd(&g_Z, v);
    }
}

// ---------------- K5: fused residual MLP (fp16 A, split-B, 2 passes) --------
// smem: sc[128] | smol[128] | A[128][APAD] fp16
#define OFF_SC  0
#define OFF_MOL 512
#define OFF_A   1024
#define SMEM_TOTAL (OFF_A + 128 * APAD * 2)

__device__ __forceinline__ void st_pair(char* sm, int r, int c, float a, float b) {
    *(unsigned*)(sm + OFF_A + (unsigned)(r * APAD + c) * 2u) = pack_h2(a, b);
}

__global__ void __launch_bounds__(256, 2)
k_mlp(const int* __restrict__ idx, float* __restrict__ out, int N) {
    extern __shared__ char sm[];
    float* sc   = (float*)(sm + OFF_SC);
    int*   smol = (int*)  (sm + OFF_MOL);
    int tid = threadIdx.x, wid = tid >> 5, lane = tid & 31;
    int n0 = blockIdx.x * 128;
    int r0 = wid * 16;

    if (tid < 128) {
        int n = n0 + tid; float c = 0.f; int m = 0;
        if (n < N) { m = idx[n]; c = g_p[n] / (g_anorm[m] + 1e-8f * g_Z); }
        sc[tid] = c; smol[tid] = m;
    }
    __syncthreads();

    // build stage-0 A tile: fp16(ssp(c * v))  (warp-local rows)
    {
        int r = tid >> 1, co = (tid & 1) * 64;
        float c = sc[r];
        const float4* vr = (const float4*)(g_v + (size_t)smol[r] * FDIM + co);
        #pragma unroll
        for (int q = 0; q < 16; q++) {
            float4 v = vr[q];
            int j = co + q * 4;
            st_pair(sm, r, j,     ssp(c * v.x), ssp(c * v.y));
            st_pair(sm, r, j + 2, ssp(c * v.z), ssp(c * v.w));
        }
    }
    __syncwarp();

    // ldmatrix source address for this lane (A frag m16k16, 4 8x8 tiles)
    int lrow = r0 + (lane & 7) + ((lane >> 3) & 1) * 8;
    int lkof = (lane >> 4) * 8;
    unsigned aA = smem_u32(sm + OFF_A) + (unsigned)(lrow * APAD + lkof) * 2u;

    int gr0 = r0 + (lane >> 2);        // epilogue rows
    int gr1 = gr0 + 8;
    int cofs = (lane & 3) * 2;         // epilogue col offset inside n-tile

    for (int s = 0; s < 3; s++) {
        float acc[16][4];
        #pragma unroll
        for (int t = 0; t < 16; t++) {
            acc[t][0] = 0.f; acc[t][1] = 0.f; acc[t][2] = 0.f; acc[t][3] = 0.f;
        }
        const uint4* Bp = g_Bf + (s * 8) * 16 * 32 + lane;

        #pragma unroll
        for (int ks = 0; ks < 8; ks++) {
            unsigned a0, a1, a2, a3;
            LDMATRIX_X4(a0, a1, a2, a3, aA + (unsigned)(ks * 32));
            #pragma unroll
            for (int t = 0; t < 16; t++) {
                uint4 b = Bp[(ks * 16 + t) * 32];
                MMA16816(acc[t][0], acc[t][1], acc[t][2], acc[t][3],
                         a0, a1, a2, a3, b.x, b.y);   // A * Bh
                MMA16816(acc[t][0], acc[t][1], acc[t][2], acc[t][3],
                         a0, a1, a2, a3, b.z, b.w);   // A * Bl
            }
        }

        if (s == 2) {
            #pragma unroll
            for (int t = 0; t < 16; t++) {
                int c = t * 8 + cofs;
                int na = n0 + gr0, nb = n0 + gr1;
                if (na < N)
                    *(float2*)(out + (size_t)na * FDIM + c) =
                        make_float2(acc[t][0], acc[t][1]);
                if (nb < N)
                    *(float2*)(out + (size_t)nb * FDIM + c) =
                        make_float2(acc[t][2], acc[t][3]);
            }
        } else if (s == 0) {
            #pragma unroll
            for (int t = 0; t < 16; t++) {
                int c = t * 8 + cofs;
                st_pair(sm, gr0, c, ssp(acc[t][0]), ssp(acc[t][1]));
                st_pair(sm, gr1, c, ssp(acc[t][2]), ssp(acc[t][3]));
            }
            __syncwarp();
        } else {
            float ca = sc[gr0], cb = sc[gr1];
            const float* va = g_v + (size_t)smol[gr0] * FDIM;
            const float* vb = g_v + (size_t)smol[gr1] * FDIM;
            #pragma unroll
            for (int t = 0; t < 16; t++) {
                int c = t * 8 + cofs;
                float2 v0 = *(const float2*)(va + c);
                float2 v1 = *(const float2*)(vb + c);
                st_pair(sm, gr0, c, ssp(ca * v0.x + acc[t][0]),
                                    ssp(ca * v0.y + acc[t][1]));
                st_pair(sm, gr1, c, ssp(cb * v1.x + acc[t][2]),
                                    ssp(cb * v1.y + acc[t][3]));
            }
            __syncwarp();
        }
    }
}

// ---------------- launcher --------------------------------------------------
extern "C" void kernel_launch(void* const* d_in, const int* in_sizes, int n_in,
                              void* d_out, int out_size) {
    const float* x  = (const float*)d_in[0];
    const float* ef = (const float*)d_in[1];
    const int*  idx = (const int*)  d_in[2];
    const float* Wq = (const float*)d_in[3];
    const float* bq = (const float*)d_in[4];
    const float* Wk = (const float*)d_in[5];
    const float* Wv = (const float*)d_in[6];
    const float* W1 = (const float*)d_in[7];
    const float* W2 = (const float*)d_in[8];
    const float* Wo = (const float*)d_in[9];
    float* out = (float*)d_out;

    int N = in_sizes[0] / FDIM;
    int B = in_sizes[1];

    cudaFuncSetAttribute(k_mlp, cudaFuncAttributeMaxDynamicSharedMemorySize,
                         SMEM_TOTAL);

    k_setup<<<49 + (B + 255) / 256, 256>>>(Wq, bq, Wk, W1, W2, Wo, B);
    k_mol<<<(B * FDIM + 255) / 256, 256>>>(ef, Wv, B);
    k_w<<<(N + 63) / 64, 256>>>(x, idx, N);
    k_p<<<(N + 255) / 256, 256>>>(idx, N);
    k_mlp<<<(N + 127) / 128, 256, SMEM_TOTAL>>>(idx, out, N);
}

// round 11
// speedup vs baseline: 4.7675x; 1.3024x over previous
#include <cuda_runtime.h>
#include <cuda_fp16.h>
#include <math.h>

#define FDIM 128
#define NMAX 400000
#define BMAX 10000
#define APAD 136

// ---------------- scratch (device globals; no runtime alloc) ----------------
__device__ float g_kq[BMAX * FDIM];
__device__ float g_v [BMAX * FDIM];
__device__ float g_kb[BMAX];
__device__ float g_M [FDIM * 2];
__device__ float g_mb[2];
__device__ float g_w [NMAX];
__device__ float g_p [NMAX];
__device__ float g_anorm[BMAX];
__device__ float g_Z;
__device__ unsigned g_maxu;
// B fragments, per-lane mma layout: [3 stages][8 ksteps][16 ntiles][32 lanes]
// uint2 = { b0, b1 }  (fp16)
__device__ uint2 g_Bf[3 * 8 * 16 * 32];

// ---------------- small helpers ---------------------------------------------
__device__ __forceinline__ unsigned f2ord(float f) {
    unsigned b = __float_as_uint(f);
    return (b & 0x80000000u) ? ~b : (b | 0x80000000u);
}
__device__ __forceinline__ float ord2f(unsigned u) {
    unsigned b = (u & 0x80000000u) ? (u & 0x7fffffffu) : ~u;
    return __uint_as_float(b);
}
__device__ __forceinline__ float ssp(float x) {
    if (x > 15.f) return x - 0.69314718055994531f;
    return __logf(1.f + __expf(x)) - 0.69314718055994531f;
}
__device__ __forceinline__ unsigned smem_u32(const void* p) {
    unsigned a;
    asm("{ .reg .u64 t; cvta.to.shared.u64 t, %1; cvt.u32.u64 %0, t; }"
        : "=r"(a) : "l"(p));
    return a;
}
__device__ __forceinline__ unsigned pack_h2(float a, float b) {
    __half2 h = __halves2half2(__float2half_rn(a), __float2half_rn(b));
    return *(unsigned*)&h;
}

// mma.sync m16n8k16 row.col fp16 -> f32 accum (arch-generic, valid at sm_103)
#define MMA16816(c0, c1, c2, c3, a0, a1, a2, a3, b0, b1) \
    asm volatile("mma.sync.aligned.m16n8k16.row.col.f32.f16.f16.f32 " \
                 "{%0,%1,%2,%3},{%4,%5,%6,%7},{%8,%9},{%0,%1,%2,%3};" \
                 : "+f"(c0), "+f"(c1), "+f"(c2), "+f"(c3) \
                 : "r"(a0), "r"(a1), "r"(a2), "r"(a3), "r"(b0), "r"(b1))

#define LDMATRIX_X4(r0, r1, r2, r3, addr) \
    asm volatile("ldmatrix.sync.aligned.m8n8.x4.shared.b16 {%0,%1,%2,%3}, [%4];" \
                 : "=r"(r0), "=r"(r1), "=r"(r2), "=r"(r3) : "r"(addr))

// ---------------- K_setup: init accumulators + prep M/mb + weight conv ------
// blocks [0,48): B-frag conversion; block 48: M/mb; blocks 49..: zero anorm
__global__ void k_setup(const float* __restrict__ Wq,
                        const float* __restrict__ bq,
                        const float* __restrict__ Wk,
                        const float* __restrict__ W1,
                        const float* __restrict__ W2,
                        const float* __restrict__ Wo, int B) {
    int blk = blockIdx.x, tid = threadIdx.x;
    if (blk < 48) {
        int i = blk * 256 + tid;                     // 12288 fragments
        int lane = i & 31, t = (i >> 5) & 15, ks = (i >> 9) & 7, s = i >> 12;
        const float* W = (s == 0) ? W1 : ((s == 1) ? W2 : Wo);
        int n  = t * 8 + (lane >> 2);
        int k0 = ks * 16 + (lane & 3) * 2;
        const float* row = W + n * FDIM;
        uint2 o;
        o.x = pack_h2(row[k0],     row[k0 + 1]);
        o.y = pack_h2(row[k0 + 8], row[k0 + 9]);
        g_Bf[i] = o;
    } else if (blk == 48) {
        int j = tid & (FDIM - 1);
        int c = tid >> 7;
        float s = 0.f;
        for (int f = 0; f < FDIM; f++) s += Wq[f * FDIM + j] * Wk[f * 2 + c];
        g_M[j * 2 + c] = s;
        if (tid < 2) {
            float sb = 0.f;
            for (int f = 0; f < FDIM; f++) sb += Wk[f * 2 + tid] * bq[f];
            g_mb[tid] = sb;
        }
    } else {
        int i = (blk - 49) * 256 + tid;
        if (i < B) g_anorm[i] = 0.f;
        if (i == 0) { g_Z = 0.f; g_maxu = 0u; }
    }
}

// ---------------- K2: per-molecule kq, v, kb --------------------------------
__global__ void k_mol(const float* __restrict__ ef,
                      const float* __restrict__ Wv, int B) {
    int i = blockIdx.x * blockDim.x + threadIdx.x;
    if (i >= B * FDIM) return;
    int m = i >> 7, f = i & (FDIM - 1);
    float e  = ef[m];
    float e0 = fmaxf(e, 0.f), e1 = fmaxf(-e, 0.f);
    float h0 = e0 / fmaxf(e0, 1.f), h1 = e1 / fmaxf(e1, 1.f);
    g_kq[i] = g_M[f * 2 + 0] * h0 + g_M[f * 2 + 1] * h1;
    g_v [i] = Wv [f * 2 + 0] * e0 + Wv [f * 2 + 1] * e1;
    if (f == 0) g_kb[m] = g_mb[0] * h0 + g_mb[1] * h1;
}

// ---------------- K3: logits + global max (8 atoms / warp) ------------------
__global__ void k_w(const float* __restrict__ x,
                    const int* __restrict__ idx, int N) {
    int warp = (blockIdx.x * blockDim.x + threadIdx.x) >> 5;
    int lane = threadIdx.x & 31;
    int base = warp * 8;
    float wmaxl = -INFINITY;

    if (base < N) {
        float s[8];
        int   m[8];
        #pragma unroll
        for (int j = 0; j < 8; j++) {
            int n = base + j;
            s[j] = 0.f; m[j] = 0;
            if (n < N) {
                m[j] = idx[n];
                float4 a = ((const float4*)(x    + (size_t)n    * FDIM))[lane];
                float4 b = ((const float4*)(g_kq + (size_t)m[j] * FDIM))[lane];
                s[j] = a.x * b.x + a.y * b.y + a.z * b.z + a.w * b.w;
            }
        }
        #pragma unroll
        for (int j = 0; j < 8; j++) {
            #pragma unroll
            for (int o = 16; o; o >>= 1) s[j] += __shfl_xor_sync(~0u, s[j], o);
        }
        #pragma unroll
        for (int j = 0; j < 8; j++) {
            int n = base + j;
            if (n < N) {
                float wv = (s[j] + g_kb[m[j]]) * 0.08838834764831844f;
                if (lane == j) g_w[n] = wv;
                wmaxl = fmaxf(wmaxl, wv);
            }
        }
    }
    __shared__ float red[8];
    if (lane == 0) red[threadIdx.x >> 5] = wmaxl;
    __syncthreads();
    if (threadIdx.x < 8) {
        float v = red[threadIdx.x];
        #pragma unroll
        for (int o = 4; o; o >>= 1) v = fmaxf(v, __shfl_xor_sync(0xffu, v, o));
        if (threadIdx.x == 0) atomicMax(&g_maxu, f2ord(v));
    }
}

// ---------------- K4: p = exp(w - wmax), Z, per-molecule sums ---------------
__global__ void k_p(const int* __restrict__ idx, int N) {
    int n = blockIdx.x * blockDim.x + threadIdx.x;
    int lane = threadIdx.x & 31;
    float wmax = ord2f(g_maxu);
    float p = 0.f; int m = -1;
    if (n < N) {
        m = idx[n];
        p = __expf(g_w[n] - wmax);
        g_p[n] = p;
    }
    // warp-aggregated segment atomic (idx sorted -> most warps uniform)
    int mf = __shfl_sync(~0u, m, 0);
    if (__all_sync(~0u, m == mf)) {
        float t = p;
        #pragma unroll
        for (int o = 16; o; o >>= 1) t += __shfl_xor_sync(~0u, t, o);
        if (lane == 0 && mf >= 0) atomicAdd(&g_anorm[mf], t);
    } else if (n < N) {
        atomicAdd(&g_anorm[m], p);
    }
    // global Z
    float z = p;
    #pragma unroll
    for (int o = 16; o; o >>= 1) z += __shfl_xor_sync(~0u, z, o);
    __shared__ float red[8];
    if (lane == 0) red[threadIdx.x >> 5] = z;
    __syncthreads();
    if (threadIdx.x < 8) {
        float v = red[threadIdx.x];
        #pragma unroll
        for (int o = 4; o; o >>= 1) v += __shfl_xor_sync(0xffu, v, o);
        if (threadIdx.x == 0) atomicAdd(&g_Z, v);
    }
}

// ---------------- K5: fused residual MLP (pure fp16, 1 pass / GEMM) ---------
// smem: sc[128] | smol[128] | A[128][APAD] fp16
#define OFF_SC  0
#define OFF_MOL 512
#define OFF_A   1024
#define SMEM_TOTAL (OFF_A + 128 * APAD * 2)

__device__ __forceinline__ void st_pair(char* sm, int r, int c, float a, float b) {
    *(unsigned*)(sm + OFF_A + (unsigned)(r * APAD + c) * 2u) = pack_h2(a, b);
}

__global__ void __launch_bounds__(256, 2)
k_mlp(const int* __restrict__ idx, float* __restrict__ out, int N) {
    extern __shared__ char sm[];
    float* sc   = (float*)(sm + OFF_SC);
    int*   smol = (int*)  (sm + OFF_MOL);
    int tid = threadIdx.x, wid = tid >> 5, lane = tid & 31;
    int n0 = blockIdx.x * 128;
    int r0 = wid * 16;

    if (tid < 128) {
        int n = n0 + tid; float c = 0.f; int m = 0;
        if (n < N) { m = idx[n]; c = g_p[n] / (g_anorm[m] + 1e-8f * g_Z); }
        sc[tid] = c; smol[tid] = m;
    }
    __syncthreads();

    // build stage-0 A tile: fp16(ssp(c * v))  (warp-local rows)
    {
        int r = tid >> 1, co = (tid & 1) * 64;
        float c = sc[r];
        const float4* vr = (const float4*)(g_v + (size_t)smol[r] * FDIM + co);
        #pragma unroll
        for (int q = 0; q < 16; q++) {
            float4 v = vr[q];
            int j = co + q * 4;
            st_pair(sm, r, j,     ssp(c * v.x), ssp(c * v.y));
            st_pair(sm, r, j + 2, ssp(c * v.z), ssp(c * v.w));
        }
    }
    __syncwarp();

    // ldmatrix source address for this lane (A frag m16k16, 4 8x8 tiles)
    int lrow = r0 + (lane & 7) + ((lane >> 3) & 1) * 8;
    int lkof = (lane >> 4) * 8;
    unsigned aA = smem_u32(sm + OFF_A) + (unsigned)(lrow * APAD + lkof) * 2u;

    int gr0 = r0 + (lane >> 2);        // epilogue rows
    int gr1 = gr0 + 8;
    int cofs = (lane & 3) * 2;         // epilogue col offset inside n-tile

    for (int s = 0; s < 3; s++) {
        float acc[16][4];
        #pragma unroll
        for (int t = 0; t < 16; t++) {
            acc[t][0] = 0.f; acc[t][1] = 0.f; acc[t][2] = 0.f; acc[t][3] = 0.f;
        }
        const uint2* Bp = g_Bf + (s * 8) * 16 * 32 + lane;

        #pragma unroll
        for (int ks = 0; ks < 8; ks++) {
            unsigned a0, a1, a2, a3;
            LDMATRIX_X4(a0, a1, a2, a3, aA + (unsigned)(ks * 32));
            #pragma unroll
            for (int t = 0; t < 16; t++) {
                uint2 b = Bp[(ks * 16 + t) * 32];
                MMA16816(acc[t][0], acc[t][1], acc[t][2], acc[t][3],
                         a0, a1, a2, a3, b.x, b.y);
            }
        }

        if (s == 2) {
            #pragma unroll
            for (int t = 0; t < 16; t++) {
                int c = t * 8 + cofs;
                int na = n0 + gr0, nb = n0 + gr1;
                if (na < N)
                    *(float2*)(out + (size_t)na * FDIM + c) =
                        make_float2(acc[t][0], acc[t][1]);
                if (nb < N)
                    *(float2*)(out + (size_t)nb * FDIM + c) =
                        make_float2(acc[t][2], acc[t][3]);
            }
        } else if (s == 0) {
            #pragma unroll
            for (int t = 0; t < 16; t++) {
                int c = t * 8 + cofs;
                st_pair(sm, gr0, c, ssp(acc[t][0]), ssp(acc[t][1]));
                st_pair(sm, gr1, c, ssp(acc[t][2]), ssp(acc[t][3]));
            }
            __syncwarp();
        } else {
            float ca = sc[gr0], cb = sc[gr1];
            const float* va = g_v + (size_t)smol[gr0] * FDIM;
            const float* vb = g_v + (size_t)smol[gr1] * FDIM;
            #pragma unroll
            for (int t = 0; t < 16; t++) {
                int c = t * 8 + cofs;
                float2 v0 = *(const float2*)(va + c);
                float2 v1 = *(const float2*)(vb + c);
                st_pair(sm, gr0, c, ssp(ca * v0.x + acc[t][0]),
                                    ssp(ca * v0.y + acc[t][1]));
                st_pair(sm, gr1, c, ssp(cb * v1.x + acc[t][2]),
                                    ssp(cb * v1.y + acc[t][3]));
            }
            __syncwarp();
        }
    }
}

// ---------------- launcher --------------------------------------------------
extern "C" void kernel_launch(void* const* d_in, const int* in_sizes, int n_in,
                              void* d_out, int out_size) {
    const float* x  = (const float*)d_in[0];
    const float* ef = (const float*)d_in[1];
    const int*  idx = (const int*)  d_in[2];
    const float* Wq = (const float*)d_in[3];
    const float* bq = (const float*)d_in[4];
    const float* Wk = (const float*)d_in[5];
    const float* Wv = (const float*)d_in[6];
    const float* W1 = (const float*)d_in[7];
    const float* W2 = (const float*)d_in[8];
    const float* Wo = (const float*)d_in[9];
    float* out = (float*)d_out;

    int N = in_sizes[0] / FDIM;
    int B = in_sizes[1];

    cudaFuncSetAttribute(k_mlp, cudaFuncAttributeMaxDynamicSharedMemorySize,
                         SMEM_TOTAL);

    k_setup<<<49 + (B + 255) / 256, 256>>>(Wq, bq, Wk, W1, W2, Wo, B);
    k_mol<<<(B * FDIM + 255) / 256, 256>>>(ef, Wv, B);
    k_w<<<(N + 63) / 64, 256>>>(x, idx, N);
    k_p<<<(N + 255) / 256, 256>>>(idx, N);
    k_mlp<<<(N + 127) / 128, 256, SMEM_TOTAL>>>(idx, out, N);
}

// round 12
// speedup vs baseline: 4.8704x; 1.0216x over previous
#include <cuda_runtime.h>
#include <cuda_fp16.h>
#include <math.h>

#define FDIM 128
#define NMAX 400000
#define BMAX 10000
#define APAD 136

// ---------------- scratch (device globals; no runtime alloc) ----------------
__device__ float g_kq[BMAX * FDIM];
__device__ float g_v [BMAX * FDIM];
__device__ float g_kb[BMAX];
__device__ float g_M [FDIM * 2];
__device__ float g_mb[2];
__device__ float g_p [NMAX];
__device__ float g_anorm[BMAX];
__device__ float g_Z;
// B fragments, per-lane mma layout: [3 stages][8 ksteps][16 ntiles][32 lanes]
__device__ uint2 g_Bf[3 * 8 * 16 * 32];

// ---------------- small helpers ---------------------------------------------
__device__ __forceinline__ float ssp(float x) {
    if (x > 15.f) return x - 0.69314718055994531f;
    return __logf(1.f + __expf(x)) - 0.69314718055994531f;
}
__device__ __forceinline__ unsigned smem_u32(const void* p) {
    unsigned a;
    asm("{ .reg .u64 t; cvta.to.shared.u64 t, %1; cvt.u32.u64 %0, t; }"
        : "=r"(a) : "l"(p));
    return a;
}
__device__ __forceinline__ unsigned pack_h2(float a, float b) {
    __half2 h = __halves2half2(__float2half_rn(a), __float2half_rn(b));
    return *(unsigned*)&h;
}

// mma.sync m16n8k16 row.col fp16 -> f32 accum (arch-generic, valid at sm_103)
#define MMA16816(c0, c1, c2, c3, a0, a1, a2, a3, b0, b1) \
    asm volatile("mma.sync.aligned.m16n8k16.row.col.f32.f16.f16.f32 " \
                 "{%0,%1,%2,%3},{%4,%5,%6,%7},{%8,%9},{%0,%1,%2,%3};" \
                 : "+f"(c0), "+f"(c1), "+f"(c2), "+f"(c3) \
                 : "r"(a0), "r"(a1), "r"(a2), "r"(a3), "r"(b0), "r"(b1))

#define LDMATRIX_X4(r0, r1, r2, r3, addr) \
    asm volatile("ldmatrix.sync.aligned.m8n8.x4.shared.b16 {%0,%1,%2,%3}, [%4];" \
                 : "=r"(r0), "=r"(r1), "=r"(r2), "=r"(r3) : "r"(addr))

// ---------------- K_setup: init accumulators + prep M/mb + weight conv ------
__global__ void k_setup(const float* __restrict__ Wq,
                        const float* __restrict__ bq,
                        const float* __restrict__ Wk,
                        const float* __restrict__ W1,
                        const float* __restrict__ W2,
                        const float* __restrict__ Wo, int B) {
    int blk = blockIdx.x, tid = threadIdx.x;
    if (blk < 48) {
        int i = blk * 256 + tid;                     // 12288 fragments
        int lane = i & 31, t = (i >> 5) & 15, ks = (i >> 9) & 7, s = i >> 12;
        const float* W = (s == 0) ? W1 : ((s == 1) ? W2 : Wo);
        int n  = t * 8 + (lane >> 2);
        int k0 = ks * 16 + (lane & 3) * 2;
        const float* row = W + n * FDIM;
        uint2 o;
        o.x = pack_h2(row[k0],     row[k0 + 1]);
        o.y = pack_h2(row[k0 + 8], row[k0 + 9]);
        g_Bf[i] = o;
    } else if (blk == 48) {
        int j = tid & (FDIM - 1);
        int c = tid >> 7;
        float s = 0.f;
        for (int f = 0; f < FDIM; f++) s += Wq[f * FDIM + j] * Wk[f * 2 + c];
        g_M[j * 2 + c] = s;
        if (tid < 2) {
            float sb = 0.f;
            for (int f = 0; f < FDIM; f++) sb += Wk[f * 2 + tid] * bq[f];
            g_mb[tid] = sb;
        }
    } else {
        int i = (blk - 49) * 256 + tid;
        if (i < B) g_anorm[i] = 0.f;
        if (i == 0) g_Z = 0.f;
    }
}

// ---------------- K2: per-molecule kq, v, kb --------------------------------
__global__ void k_mol(const float* __restrict__ ef,
                      const float* __restrict__ Wv, int B) {
    int i = blockIdx.x * blockDim.x + threadIdx.x;
    if (i >= B * FDIM) return;
    int m = i >> 7, f = i & (FDIM - 1);
    float e  = ef[m];
    float e0 = fmaxf(e, 0.f), e1 = fmaxf(-e, 0.f);
    float h0 = e0 / fmaxf(e0, 1.f), h1 = e1 / fmaxf(e1, 1.f);
    g_kq[i] = g_M[f * 2 + 0] * h0 + g_M[f * 2 + 1] * h1;
    g_v [i] = Wv [f * 2 + 0] * e0 + Wv [f * 2 + 1] * e1;
    if (f == 0) g_kb[m] = g_mb[0] * h0 + g_mb[1] * h1;
}

// ---------------- K3: logits -> p = exp(w) (no max pass), anorm, Z ----------
// max-subtraction cancels in p/(sum_p + 1e-8*Z); |w| small enough for exp
__global__ void k_w(const float* __restrict__ x,
                    const int* __restrict__ idx, int N) {
    int warp = (blockIdx.x * blockDim.x + threadIdx.x) >> 5;
    int lane = threadIdx.x & 31;
    int base = warp * 8;
    float pv = 0.f; int pm = -1;
    int mfirst = 0, mlast = 0;

    if (base < N) {
        float s[8];
        int   m[8];
        #pragma unroll
        for (int j = 0; j < 8; j++) {
            int n = base + j;
            s[j] = 0.f; m[j] = 0;
            if (n < N) {
                m[j] = idx[n];
                float4 a = ((const float4*)(x    + (size_t)n    * FDIM))[lane];
                float4 b = ((const float4*)(g_kq + (size_t)m[j] * FDIM))[lane];
                s[j] = a.x * b.x + a.y * b.y + a.z * b.z + a.w * b.w;
            }
        }
        #pragma unroll
        for (int j = 0; j < 8; j++) {
            #pragma unroll
            for (int o = 16; o; o >>= 1) s[j] += __shfl_xor_sync(~0u, s[j], o);
        }
        #pragma unroll
        for (int j = 0; j < 8; j++) {
            int n = base + j;
            if (lane == j && n < N) {
                pv = __expf((s[j] + g_kb[m[j]]) * 0.08838834764831844f);
                pm = m[j];
                g_p[n] = pv;
            }
        }
        mfirst = m[0];
        mlast  = m[(N - base >= 8) ? 7 : (N - 1 - base)];
    }

    // per-molecule sums (idx sorted -> usually one molecule per 8-atom group)
    if (base < N && mfirst == mlast) {
        float t = pv;
        #pragma unroll
        for (int o = 16; o; o >>= 1) t += __shfl_xor_sync(~0u, t, o);
        if (lane == 0) atomicAdd(&g_anorm[mfirst], t);
    } else if (pm >= 0) {
        atomicAdd(&g_anorm[pm], pv);
    }

    // global Z
    float z = pv;
    #pragma unroll
    for (int o = 16; o; o >>= 1) z += __shfl_xor_sync(~0u, z, o);
    __shared__ float red[8];
    if (lane == 0) red[threadIdx.x >> 5] = z;
    __syncthreads();
    if (threadIdx.x < 8) {
        float v = red[threadIdx.x];
        #pragma unroll
        for (int o = 4; o; o >>= 1) v += __shfl_xor_sync(0xffu, v, o);
        if (threadIdx.x == 0) atomicAdd(&g_Z, v);
    }
}

// ---------------- K5: fused residual MLP (fp16 HMMA, t-outer pipeline) ------
// smem: sc[128] | smol[128] | A[128][APAD] fp16
#define OFF_SC  0
#define OFF_MOL 512
#define OFF_A   1024
#define SMEM_TOTAL (OFF_A + 128 * APAD * 2)

__device__ __forceinline__ void st_pair(char* sm, int r, int c, float a, float b) {
    *(unsigned*)(sm + OFF_A + (unsigned)(r * APAD + c) * 2u) = pack_h2(a, b);
}

__global__ void __launch_bounds__(256, 3)
k_mlp(const int* __restrict__ idx, float* __restrict__ out, int N) {
    extern __shared__ char sm[];
    float* sc   = (float*)(sm + OFF_SC);
    int*   smol = (int*)  (sm + OFF_MOL);
    int tid = threadIdx.x, wid = tid >> 5, lane = tid & 31;
    int n0 = blockIdx.x * 128;
    int r0 = wid * 16;

    if (tid < 128) {
        int n = n0 + tid; float c = 0.f; int m = 0;
        if (n < N) { m = idx[n]; c = g_p[n] / (g_anorm[m] + 1e-8f * g_Z); }
        sc[tid] = c; smol[tid] = m;
    }
    __syncthreads();

    // build stage-0 A tile: fp16(ssp(c * v))  (warp-local rows)
    {
        int r = tid >> 1, co = (tid & 1) * 64;
        float c = sc[r];
        const float4* vr = (const float4*)(g_v + (size_t)smol[r] * FDIM + co);
        #pragma unroll
        for (int q = 0; q < 16; q++) {
            float4 v = vr[q];
            int j = co + q * 4;
            st_pair(sm, r, j,     ssp(c * v.x), ssp(c * v.y));
            st_pair(sm, r, j + 2, ssp(c * v.z), ssp(c * v.w));
        }
    }
    __syncwarp();

    // ldmatrix source address for this lane (A frag m16k16, 4 8x8 tiles)
    int lrow = r0 + (lane & 7) + ((lane >> 3) & 1) * 8;
    int lkof = (lane >> 4) * 8;
    unsigned aA = smem_u32(sm + OFF_A) + (unsigned)(lrow * APAD + lkof) * 2u;

    int gr0 = r0 + (lane >> 2);        // epilogue rows
    int gr1 = gr0 + 8;
    int cofs = (lane & 3) * 2;         // epilogue col offset inside n-tile

    for (int s = 0; s < 3; s++) {
        // preload all A fragments for this stage (32 regs)
        unsigned af[8][4];
        #pragma unroll
        for (int ks = 0; ks < 8; ks++)
            LDMATRIX_X4(af[ks][0], af[ks][1], af[ks][2], af[ks][3],
                        aA + (unsigned)(ks * 32));

        const uint2* Bp = g_Bf + (s * 8) * 16 * 32 + lane;
        float ca = 0.f, cb = 0.f;
        const float* va = 0; const float* vb = 0;
        if (s == 1) {
            ca = sc[gr0]; cb = sc[gr1];
            va = g_v + (size_t)smol[gr0] * FDIM;
            vb = g_v + (size_t)smol[gr1] * FDIM;
        }

        // t-outer: per-tile MMA chain + immediate epilogue (2-way interleave)
        #pragma unroll
        for (int tp = 0; tp < 8; tp++) {
            int t0 = tp, t1 = tp + 8;
            float x0 = 0.f, x1 = 0.f, x2 = 0.f, x3 = 0.f;
            float y0 = 0.f, y1 = 0.f, y2 = 0.f, y3 = 0.f;
            #pragma unroll
            for (int ks = 0; ks < 8; ks++) {
                uint2 b0 = Bp[(ks * 16 + t0) * 32];
                uint2 b1 = Bp[(ks * 16 + t1) * 32];
                MMA16816(x0, x1, x2, x3,
                         af[ks][0], af[ks][1], af[ks][2], af[ks][3], b0.x, b0.y);
                MMA16816(y0, y1, y2, y3,
                         af[ks][0], af[ks][1], af[ks][2], af[ks][3], b1.x, b1.y);
            }
            int c0 = t0 * 8 + cofs, c1 = t1 * 8 + cofs;
            if (s == 2) {
                int na = n0 + gr0, nb = n0 + gr1;
                if (na < N) {
                    *(float2*)(out + (size_t)na * FDIM + c0) = make_float2(x0, x1);
                    *(float2*)(out + (size_t)na * FDIM + c1) = make_float2(y0, y1);
                }
                if (nb < N) {
                    *(float2*)(out + (size_t)nb * FDIM + c0) = make_float2(x2, x3);
                    *(float2*)(out + (size_t)nb * FDIM + c1) = make_float2(y2, y3);
                }
            } else if (s == 0) {
                st_pair(sm, gr0, c0, ssp(x0), ssp(x1));
                st_pair(sm, gr1, c0, ssp(x2), ssp(x3));
                st_pair(sm, gr0, c1, ssp(y0), ssp(y1));
                st_pair(sm, gr1, c1, ssp(y2), ssp(y3));
            } else {
                float2 v0a = *(const float2*)(va + c0);
                float2 v0b = *(const float2*)(vb + c0);
                float2 v1a = *(const float2*)(va + c1);
                float2 v1b = *(const float2*)(vb + c1);
                st_pair(sm, gr0, c0, ssp(ca * v0a.x + x0), ssp(ca * v0a.y + x1));
                st_pair(sm, gr1, c0, ssp(cb * v0b.x + x2), ssp(cb * v0b.y + x3));
                st_pair(sm, gr0, c1, ssp(ca * v1a.x + y0), ssp(ca * v1a.y + y1));
                st_pair(sm, gr1, c1, ssp(cb * v1b.x + y2), ssp(cb * v1b.y + y3));
            }
        }
        if (s < 2) __syncwarp();
    }
}

// ---------------- launcher --------------------------------------------------
extern "C" void kernel_launch(void* const* d_in, const int* in_sizes, int n_in,
                              void* d_out, int out_size) {
    const float* x  = (const float*)d_in[0];
    const float* ef = (const float*)d_in[1];
    const int*  idx = (const int*)  d_in[2];
    const float* Wq = (const float*)d_in[3];
    const float* bq = (const float*)d_in[4];
    const float* Wk = (const float*)d_in[5];
    const float* Wv = (const float*)d_in[6];
    const float* W1 = (const float*)d_in[7];
    const float* W2 = (const float*)d_in[8];
    const float* Wo = (const float*)d_in[9];
    float* out = (float*)d_out;

    int N = in_sizes[0] / FDIM;
    int B = in_sizes[1];

    cudaFuncSetAttribute(k_mlp, cudaFuncAttributeMaxDynamicSharedMemorySize,
                         SMEM_TOTAL);

    k_setup<<<49 + (B + 255) / 256, 256>>>(Wq, bq, Wk, W1, W2, Wo, B);
    k_mol<<<(B * FDIM + 255) / 256, 256>>>(ef, Wv, B);
    k_w<<<(N + 63) / 64, 256>>>(x, idx, N);
    k_mlp<<<(N + 127) / 128, 256, SMEM_TOTAL>>>(idx, out, N);
}